// round 2
// baseline (speedup 1.0000x reference)
#include <cuda_runtime.h>
#include <math.h>

// ---------------- Config ----------------
#define BB     8
#define CC     3
#define HH     384
#define WW     384
#define PP     16
#define DD     768
#define NHH    12
#define MLPD   3072
#define LL     12
#define NCLS   1000
#define GHH    24
#define GWW    24
#define NPAT   576          // patches
#define NTOK   577          // +CLS
#define HDIM   64
#define MTOK   (BB*NTOK)    // 4616
#define MPAD   4672         // 73*64
#define MPATCH (BB*NPAT)    // 4608 = 72*64

// ---------------- Scratch (device globals; .bss zero-init) ----------------
__device__ float g_t  [MPATCH*DD];
__device__ float g_emb[MPATCH*DD];
__device__ float g_h  [MPAD*DD];
__device__ float g_y  [MPAD*DD];
__device__ float g_q  [MPAD*DD];
__device__ float g_k  [MPAD*DD];
__device__ float g_v  [MPAD*DD];
__device__ float g_ao [MPAD*DD];
__device__ float g_mlp[MPAD*MLPD];
__device__ float g_cls[BB*DD];

// ---------------- Patch gather (faithful batch-mixing flatten) ----------------
// reference order: reshape(1,P,B*C*GH*GW,P) enumeration -> [B, NP, P*P*C]
__global__ void patch_k(const float* __restrict__ x, float* __restrict__ t) {
    int idx = blockIdx.x * 256 + threadIdx.x;
    if (idx >= MPATCH * DD) return;
    int p1  = idx / 221184;          // 221184 = B*C*GH*GW*P
    int rem = idx % 221184;
    int b   = rem / 27648;  rem %= 27648;   // 27648 = C*GH*GW*P
    int c   = rem / 9216;   rem %= 9216;    // 9216  = GH*GW*P
    int gh  = rem / 384;    rem %= 384;     // 384   = GW*P
    int gw  = rem / 16;
    int p2  = rem % 16;
    t[idx] = x[(((b*CC + c)*HH) + gh*PP + p1) * WW + gw*PP + p2];
}

// ---------------- Assemble: CLS + pos_emb ----------------
__global__ void assemble_k(const float* __restrict__ emb, const float* __restrict__ cls_emb,
                           const float* __restrict__ pos, float* __restrict__ h) {
    int idx = blockIdx.x * 256 + threadIdx.x;
    if (idx >= BB * NTOK * DD) return;
    int d = idx % DD;
    int n = (idx / DD) % NTOK;
    int b = idx / (DD * NTOK);
    float val = (n == 0) ? cls_emb[d] : emb[((size_t)b*NPAT + (n-1))*DD + d];
    h[idx] = val + pos[n*DD + d];
}

// ---------------- GEMM: C = epilogue(A[M,K] @ W[K,N] + bias) ----------------
// mode 0: +bias, mode 1: +bias+C (residual), mode 2: gelu_exact(+bias)
__global__ void gemm_k(const float* __restrict__ A, const float* __restrict__ W,
                       const float* __restrict__ bias, float* __restrict__ C,
                       int M, int N, int K, int mode) {
    __shared__ float As[16][68];
    __shared__ float Bs[16][64];
    const int tid = threadIdx.x;
    const int tx = tid & 15;
    const int ty = tid >> 4;
    const int row0 = blockIdx.y * 64;
    const int col0 = blockIdx.x * 64;

    float acc[4][4];
#pragma unroll
    for (int i = 0; i < 4; i++)
#pragma unroll
        for (int j = 0; j < 4; j++) acc[i][j] = 0.f;

    const int am = tid >> 2;            // 0..63
    const int ak = (tid & 3) << 2;      // 0,4,8,12
    const int bk = tid >> 4;            // 0..15
    const int bn = (tid & 15) << 2;     // 0..60

    for (int k0 = 0; k0 < K; k0 += 16) {
        float4 av = *reinterpret_cast<const float4*>(&A[(size_t)(row0 + am)*K + k0 + ak]);
        As[ak+0][am] = av.x; As[ak+1][am] = av.y; As[ak+2][am] = av.z; As[ak+3][am] = av.w;
        float4 bv = *reinterpret_cast<const float4*>(&W[(size_t)(k0 + bk)*N + col0 + bn]);
        *reinterpret_cast<float4*>(&Bs[bk][bn]) = bv;
        __syncthreads();
#pragma unroll
        for (int kk = 0; kk < 16; kk++) {
            float a[4], b[4];
#pragma unroll
            for (int i = 0; i < 4; i++) a[i] = As[kk][ty*4 + i];
#pragma unroll
            for (int j = 0; j < 4; j++) b[j] = Bs[kk][tx*4 + j];
#pragma unroll
            for (int i = 0; i < 4; i++)
#pragma unroll
                for (int j = 0; j < 4; j++) acc[i][j] = fmaf(a[i], b[j], acc[i][j]);
        }
        __syncthreads();
    }
#pragma unroll
    for (int i = 0; i < 4; i++) {
        int r = row0 + ty*4 + i;
        if (r >= M) continue;
#pragma unroll
        for (int j = 0; j < 4; j++) {
            int cidx = col0 + tx*4 + j;
            float v = acc[i][j] + bias[cidx];
            if (mode == 1)      v += C[(size_t)r*N + cidx];
            else if (mode == 2) v = 0.5f * v * (1.0f + erff(v * 0.70710678118654752f));
            C[(size_t)r*N + cidx] = v;
        }
    }
}

// ---------------- LayerNorm (two-pass, matches reference) ----------------
__global__ void ln_k(const float* __restrict__ in, float* __restrict__ out,
                     const float* __restrict__ g, const float* __restrict__ b,
                     long in_stride) {
    const int row = blockIdx.x;
    const float* x = in + (size_t)row * in_stride;
    float* o = out + (size_t)row * DD;
    __shared__ float red[256];
    const int tid = threadIdx.x;

    float s = 0.f;
    for (int i = tid; i < DD; i += 256) s += x[i];
    red[tid] = s; __syncthreads();
    for (int off = 128; off > 0; off >>= 1) { if (tid < off) red[tid] += red[tid + off]; __syncthreads(); }
    const float mean = red[0] * (1.0f / DD);
    __syncthreads();

    float vs = 0.f;
    for (int i = tid; i < DD; i += 256) { float d = x[i] - mean; vs += d * d; }
    red[tid] = vs; __syncthreads();
    for (int off = 128; off > 0; off >>= 1) { if (tid < off) red[tid] += red[tid + off]; __syncthreads(); }
    const float rstd = rsqrtf(red[0] * (1.0f / DD) + 1e-5f);

    for (int i = tid; i < DD; i += 256) o[i] = (x[i] - mean) * rstd * g[i] + b[i];
}

// ---------------- Attention: one block per (b, head, query) ----------------
__global__ void attn_k(const float* __restrict__ q, const float* __restrict__ k,
                       const float* __restrict__ v, float* __restrict__ out) {
    const int i = blockIdx.x;     // query 0..576
    const int h = blockIdx.y;     // head  0..11
    const int b = blockIdx.z;     // batch 0..7
    const int tid = threadIdx.x;  // 256 threads
    __shared__ float s[NTOK];
    __shared__ float qs[HDIM];
    __shared__ float red[256];
    __shared__ float part[4][HDIM];
    const size_t base = ((size_t)b * NTOK) * DD + h * HDIM;

    if (tid < HDIM) qs[tid] = q[base + (size_t)i * DD + tid];
    __syncthreads();

    // scores + max
    float lmax = -1e30f;
    for (int j = tid; j < NTOK; j += 256) {
        const float* kr = &k[base + (size_t)j * DD];
        float d = 0.f;
#pragma unroll 16
        for (int t = 0; t < HDIM; t++) d = fmaf(qs[t], kr[t], d);
        d *= 0.125f;
        s[j] = d;
        lmax = fmaxf(lmax, d);
    }
    red[tid] = lmax; __syncthreads();
    for (int off = 128; off > 0; off >>= 1) { if (tid < off) red[tid] = fmaxf(red[tid], red[tid + off]); __syncthreads(); }
    const float mx = red[0];
    __syncthreads();

    // exp + sum
    float lsum = 0.f;
    for (int j = tid; j < NTOK; j += 256) {
        float e = expf(s[j] - mx);
        s[j] = e;
        lsum += e;
    }
    red[tid] = lsum; __syncthreads();
    for (int off = 128; off > 0; off >>= 1) { if (tid < off) red[tid] += red[tid + off]; __syncthreads(); }
    const float inv = 1.0f / red[0];

    // weighted sum over V: thread = (partition, dim)
    const int d = tid & (HDIM - 1);
    const int p = tid >> 6;
    float acc = 0.f;
    for (int j = p; j < NTOK; j += 4)
        acc = fmaf(s[j], v[base + (size_t)j * DD + d], acc);
    part[p][d] = acc;
    __syncthreads();
    if (tid < HDIM) {
        float o = (part[0][tid] + part[1][tid] + part[2][tid] + part[3][tid]) * inv;
        out[base + (size_t)i * DD + tid] = o;
    }
}

// ---------------- Head: logits = cls @ head_w + head_b ----------------
__global__ void head_k(const float* __restrict__ cls, const float* __restrict__ hw,
                       const float* __restrict__ hb, float* __restrict__ out) {
    int idx = blockIdx.x * 256 + threadIdx.x;
    if (idx >= BB * NCLS) return;
    int b = idx / NCLS, c = idx % NCLS;
    const float* xr = &cls[b * DD];
    float acc = hb[c];
    for (int kk = 0; kk < DD; kk++) acc = fmaf(xr[kk], hw[kk * NCLS + c], acc);
    out[idx] = acc;
}

// ---------------- Launch ----------------
extern "C" void kernel_launch(void* const* d_in, const int* in_sizes, int n_in,
                              void* d_out, int out_size) {
    const float* x       = (const float*)d_in[0];
    const float* proj_w  = (const float*)d_in[1];
    const float* proj_b  = (const float*)d_in[2];
    const float* cls_emb = (const float*)d_in[3];
    const float* pos_emb = (const float*)d_in[4];
    const float* ln1_g   = (const float*)d_in[5];
    const float* ln1_b   = (const float*)d_in[6];
    const float* qw      = (const float*)d_in[7];
    const float* qb      = (const float*)d_in[8];
    const float* kw      = (const float*)d_in[9];
    const float* kb      = (const float*)d_in[10];
    const float* vw      = (const float*)d_in[11];
    const float* vb      = (const float*)d_in[12];
    const float* ow      = (const float*)d_in[13];
    const float* ob      = (const float*)d_in[14];
    const float* ln2_g   = (const float*)d_in[15];
    const float* ln2_b   = (const float*)d_in[16];
    const float* fcw     = (const float*)d_in[17];
    const float* fcb     = (const float*)d_in[18];
    const float* pw      = (const float*)d_in[19];
    const float* pb      = (const float*)d_in[20];
    const float* lnf_g   = (const float*)d_in[21];
    const float* lnf_b   = (const float*)d_in[22];
    const float* head_w  = (const float*)d_in[23];
    const float* head_b  = (const float*)d_in[24];
    float* out = (float*)d_out;
    (void)in_sizes; (void)n_in; (void)out_size;

    float *bt, *bemb, *bh, *by, *bq, *bk, *bv, *bao, *bmlp, *bcls;
    cudaGetSymbolAddress((void**)&bt,   g_t);
    cudaGetSymbolAddress((void**)&bemb, g_emb);
    cudaGetSymbolAddress((void**)&bh,   g_h);
    cudaGetSymbolAddress((void**)&by,   g_y);
    cudaGetSymbolAddress((void**)&bq,   g_q);
    cudaGetSymbolAddress((void**)&bk,   g_k);
    cudaGetSymbolAddress((void**)&bv,   g_v);
    cudaGetSymbolAddress((void**)&bao,  g_ao);
    cudaGetSymbolAddress((void**)&bmlp, g_mlp);
    cudaGetSymbolAddress((void**)&bcls, g_cls);

    // Patch embed
    patch_k<<<(MPATCH*DD + 255)/256, 256>>>(x, bt);
    gemm_k<<<dim3(DD/64, MPATCH/64), 256>>>(bt, proj_w, proj_b, bemb, MPATCH, DD, DD, 0);
    assemble_k<<<(BB*NTOK*DD + 255)/256, 256>>>(bemb, cls_emb, pos_emb, bh);

    const int MB = (MTOK + 63) / 64;  // 73
    for (int l = 0; l < LL; l++) {
        const size_t wo  = (size_t)l * DD * DD;
        const size_t wfc = (size_t)l * DD * MLPD;

        ln_k<<<MTOK, 256>>>(bh, by, ln1_g + l*DD, ln1_b + l*DD, DD);
        gemm_k<<<dim3(DD/64, MB), 256>>>(by, qw + wo, qb + l*DD, bq, MTOK, DD, DD, 0);
        gemm_k<<<dim3(DD/64, MB), 256>>>(by, kw + wo, kb + l*DD, bk, MTOK, DD, DD, 0);
        gemm_k<<<dim3(DD/64, MB), 256>>>(by, vw + wo, vb + l*DD, bv, MTOK, DD, DD, 0);
        attn_k<<<dim3(NTOK, NHH, BB), 256>>>(bq, bk, bv, bao);
        gemm_k<<<dim3(DD/64, MB), 256>>>(bao, ow + wo, ob + l*DD, bh, MTOK, DD, DD, 1);

        ln_k<<<MTOK, 256>>>(bh, by, ln2_g + l*DD, ln2_b + l*DD, DD);
        gemm_k<<<dim3(MLPD/64, MB), 256>>>(by, fcw + wfc, fcb + l*MLPD, bmlp, MTOK, MLPD, DD, 2);
        gemm_k<<<dim3(DD/64, MB), 256>>>(bmlp, pw + wfc, pb + l*DD, bh, MTOK, DD, MLPD, 1);
    }

    // Final LN on the 8 CLS rows only, then head
    ln_k<<<BB, 256>>>(bh, bcls, lnf_g, lnf_b, (long)NTOK * DD);
    head_k<<<(BB*NCLS + 255)/256, 256>>>(bcls, head_w, head_b, out);
}

// round 4
// speedup vs baseline: 1.1416x; 1.1416x over previous
#include <cuda_runtime.h>
#include <math.h>

// ---------------- Config ----------------
#define BB     8
#define CC     3
#define HH     384
#define WW     384
#define PP     16
#define DD     768
#define NHH    12
#define MLPD   3072
#define LL     12
#define NCLS   1000
#define NPAT   576
#define NTOK   577
#define HDIM   64
#define MTOK   (BB*NTOK)    // 4616
#define MPAD   4736         // 37*128
#define MPATCH (BB*NPAT)    // 4608 = 36*128

// ---------------- Scratch (device globals; .bss zero-init) ----------------
__device__ float g_t  [MPATCH*DD];
__device__ float g_emb[MPATCH*DD];
__device__ float g_h  [MPAD*DD];
__device__ float g_y  [MPAD*DD];
__device__ float g_q  [MPAD*DD];
__device__ float g_k  [MPAD*DD];
__device__ float g_v  [MPAD*DD];
__device__ float g_ao [MPAD*DD];
__device__ float g_mlp[MPAD*MLPD];
__device__ float g_cls[BB*DD];

// ---------------- Patch gather (faithful batch-mixing flatten) ----------------
__global__ void patch_k(const float* __restrict__ x, float* __restrict__ t) {
    int idx = blockIdx.x * 256 + threadIdx.x;
    if (idx >= MPATCH * DD) return;
    int p1  = idx / 221184;          // B*C*GH*GW*P
    int rem = idx % 221184;
    int b   = rem / 27648;  rem %= 27648;
    int c   = rem / 9216;   rem %= 9216;
    int gh  = rem / 384;    rem %= 384;
    int gw  = rem / 16;
    int p2  = rem % 16;
    t[idx] = x[(((b*CC + c)*HH) + gh*PP + p1) * WW + gw*PP + p2];
}

// ---------------- Assemble: CLS + pos_emb ----------------
__global__ void assemble_k(const float* __restrict__ emb, const float* __restrict__ cls_emb,
                           const float* __restrict__ pos, float* __restrict__ h) {
    int idx = blockIdx.x * 256 + threadIdx.x;
    if (idx >= BB * NTOK * DD) return;
    int d = idx % DD;
    int n = (idx / DD) % NTOK;
    int b = idx / (DD * NTOK);
    float val = (n == 0) ? cls_emb[d] : emb[((size_t)b*NPAT + (n-1))*DD + d];
    h[idx] = val + pos[n*DD + d];
}

// ---------------- TF32 tensor-core GEMM ----------------
// C = epilogue(A[M,K] @ W[K,N] + bias); mode 0:+bias, 1:+bias+C, 2:gelu(+bias)
#define APAD 20
#define BPAD 136

__device__ __forceinline__ unsigned f2tf32(float x) {
    unsigned u;
    asm("cvt.rna.tf32.f32 %0, %1;" : "=r"(u) : "f"(x));
    return u;
}

__device__ __forceinline__ void mma_tf32(float* d, const unsigned* a, const unsigned* b) {
    asm volatile(
        "mma.sync.aligned.m16n8k8.row.col.f32.tf32.tf32.f32 "
        "{%0,%1,%2,%3}, {%4,%5,%6,%7}, {%8,%9}, {%0,%1,%2,%3};"
        : "+f"(d[0]), "+f"(d[1]), "+f"(d[2]), "+f"(d[3])
        : "r"(a[0]), "r"(a[1]), "r"(a[2]), "r"(a[3]), "r"(b[0]), "r"(b[1]));
}

__global__ void __launch_bounds__(256, 2)
gemm_tf32_k(const float* __restrict__ A, const float* __restrict__ W,
            const float* __restrict__ bias, float* __restrict__ C,
            int M, int N, int K, int mode) {
    __shared__ unsigned As[128 * APAD];   // [m][k], pad 20 -> conflict-free frag loads
    __shared__ unsigned Bs[16 * BPAD];    // [k][n], pad 136

    const int tid  = threadIdx.x;
    const int lane = tid & 31;
    const int warp = tid >> 5;
    const int wm   = warp & 1;            // 0..1 -> 64-row slab
    const int wn   = warp >> 1;           // 0..3 -> 32-col slab
    const int gid  = lane >> 2;           // 0..7
    const int tig  = lane & 3;            // 0..3
    const int row0 = blockIdx.y * 128;
    const int col0 = blockIdx.x * 128;

    float acc[4][4][4];
#pragma unroll
    for (int i = 0; i < 4; i++)
#pragma unroll
        for (int j = 0; j < 4; j++)
#pragma unroll
            for (int c = 0; c < 4; c++) acc[i][j][c] = 0.f;

    for (int k0 = 0; k0 < K; k0 += 16) {
        // load A tile: 128x16
#pragma unroll
        for (int it = 0; it < 2; it++) {
            int idx = tid + it * 256;
            int r = idx >> 2, c4 = (idx & 3) << 2;
            float4 v = *reinterpret_cast<const float4*>(&A[(size_t)(row0 + r) * K + k0 + c4]);
            unsigned* dst = &As[r * APAD + c4];
            dst[0] = f2tf32(v.x); dst[1] = f2tf32(v.y);
            dst[2] = f2tf32(v.z); dst[3] = f2tf32(v.w);
        }
        // load B tile: 16x128
#pragma unroll
        for (int it = 0; it < 2; it++) {
            int idx = tid + it * 256;
            int kk = idx >> 5, n4 = (idx & 31) << 2;
            float4 v = *reinterpret_cast<const float4*>(&W[(size_t)(k0 + kk) * N + col0 + n4]);
            unsigned* dst = &Bs[kk * BPAD + n4];
            dst[0] = f2tf32(v.x); dst[1] = f2tf32(v.y);
            dst[2] = f2tf32(v.z); dst[3] = f2tf32(v.w);
        }
        __syncthreads();

#pragma unroll
        for (int ks = 0; ks < 16; ks += 8) {
            unsigned af[4][4], bf[4][2];
#pragma unroll
            for (int mt = 0; mt < 4; mt++) {
                int r = wm * 64 + mt * 16 + gid;
                af[mt][0] = As[(r    ) * APAD + ks + tig    ];
                af[mt][1] = As[(r + 8) * APAD + ks + tig    ];
                af[mt][2] = As[(r    ) * APAD + ks + tig + 4];
                af[mt][3] = As[(r + 8) * APAD + ks + tig + 4];
            }
#pragma unroll
            for (int nt = 0; nt < 4; nt++) {
                int n = wn * 32 + nt * 8 + gid;
                bf[nt][0] = Bs[(ks + tig    ) * BPAD + n];
                bf[nt][1] = Bs[(ks + tig + 4) * BPAD + n];
            }
#pragma unroll
            for (int mt = 0; mt < 4; mt++)
#pragma unroll
                for (int nt = 0; nt < 4; nt++)
                    mma_tf32(acc[mt][nt], af[mt], bf[nt]);
        }
        __syncthreads();
    }

    // epilogue
#pragma unroll
    for (int mt = 0; mt < 4; mt++) {
#pragma unroll
        for (int nt = 0; nt < 4; nt++) {
#pragma unroll
            for (int c = 0; c < 4; c++) {
                int r   = row0 + wm * 64 + mt * 16 + gid + ((c >> 1) << 3);
                int col = col0 + wn * 32 + nt * 8 + tig * 2 + (c & 1);
                if (r >= M) continue;
                float v = acc[mt][nt][c] + bias[col];
                if (mode == 1)      v += C[(size_t)r * N + col];
                else if (mode == 2) v = 0.5f * v * (1.0f + erff(v * 0.70710678118654752f));
                C[(size_t)r * N + col] = v;
            }
        }
    }
}

// ---------------- LayerNorm ----------------
__global__ void ln_k(const float* __restrict__ in, float* __restrict__ out,
                     const float* __restrict__ g, const float* __restrict__ b,
                     long in_stride) {
    const int row = blockIdx.x;
    const float* x = in + (size_t)row * in_stride;
    float* o = out + (size_t)row * DD;
    __shared__ float red[256];
    const int tid = threadIdx.x;

    float s = 0.f;
    for (int i = tid; i < DD; i += 256) s += x[i];
    red[tid] = s; __syncthreads();
    for (int off = 128; off > 0; off >>= 1) { if (tid < off) red[tid] += red[tid + off]; __syncthreads(); }
    const float mean = red[0] * (1.0f / DD);
    __syncthreads();

    float vs = 0.f;
    for (int i = tid; i < DD; i += 256) { float d = x[i] - mean; vs += d * d; }
    red[tid] = vs; __syncthreads();
    for (int off = 128; off > 0; off >>= 1) { if (tid < off) red[tid] += red[tid + off]; __syncthreads(); }
    const float rstd = rsqrtf(red[0] * (1.0f / DD) + 1e-5f);

    for (int i = tid; i < DD; i += 256) o[i] = (x[i] - mean) * rstd * g[i] + b[i];
}

// ---------------- Attention: one block per (b, head, query) ----------------
__global__ void attn_k(const float* __restrict__ q, const float* __restrict__ k,
                       const float* __restrict__ v, float* __restrict__ out) {
    const int i = blockIdx.x;
    const int h = blockIdx.y;
    const int b = blockIdx.z;
    const int tid = threadIdx.x;
    __shared__ float s[NTOK];
    __shared__ float qs[HDIM];
    __shared__ float red[256];
    __shared__ float part[4][HDIM];
    const size_t base = ((size_t)b * NTOK) * DD + h * HDIM;

    if (tid < HDIM) qs[tid] = q[base + (size_t)i * DD + tid];
    __syncthreads();

    float lmax = -1e30f;
    for (int j = tid; j < NTOK; j += 256) {
        const float* kr = &k[base + (size_t)j * DD];
        float d = 0.f;
#pragma unroll 16
        for (int t = 0; t < HDIM; t++) d = fmaf(qs[t], kr[t], d);
        d *= 0.125f;
        s[j] = d;
        lmax = fmaxf(lmax, d);
    }
    red[tid] = lmax; __syncthreads();
    for (int off = 128; off > 0; off >>= 1) { if (tid < off) red[tid] = fmaxf(red[tid], red[tid + off]); __syncthreads(); }
    const float mx = red[0];
    __syncthreads();

    float lsum = 0.f;
    for (int j = tid; j < NTOK; j += 256) {
        float e = expf(s[j] - mx);
        s[j] = e;
        lsum += e;
    }
    red[tid] = lsum; __syncthreads();
    for (int off = 128; off > 0; off >>= 1) { if (tid < off) red[tid] += red[tid + off]; __syncthreads(); }
    const float inv = 1.0f / red[0];

    const int d = tid & (HDIM - 1);
    const int p = tid >> 6;
    float acc = 0.f;
    for (int j = p; j < NTOK; j += 4)
        acc = fmaf(s[j], v[base + (size_t)j * DD + d], acc);
    part[p][d] = acc;
    __syncthreads();
    if (tid < HDIM) {
        float o = (part[0][tid] + part[1][tid] + part[2][tid] + part[3][tid]) * inv;
        out[base + (size_t)i * DD + tid] = o;
    }
}

// ---------------- Head ----------------
__global__ void head_k(const float* __restrict__ cls, const float* __restrict__ hw,
                       const float* __restrict__ hb, float* __restrict__ out) {
    int idx = blockIdx.x * 256 + threadIdx.x;
    if (idx >= BB * NCLS) return;
    int b = idx / NCLS, c = idx % NCLS;
    const float* xr = &cls[b * DD];
    float acc = hb[c];
    for (int kk = 0; kk < DD; kk++) acc = fmaf(xr[kk], hw[kk * NCLS + c], acc);
    out[idx] = acc;
}

// ---------------- Launch ----------------
extern "C" void kernel_launch(void* const* d_in, const int* in_sizes, int n_in,
                              void* d_out, int out_size) {
    const float* x       = (const float*)d_in[0];
    const float* proj_w  = (const float*)d_in[1];
    const float* proj_b  = (const float*)d_in[2];
    const float* cls_emb = (const float*)d_in[3];
    const float* pos_emb = (const float*)d_in[4];
    const float* ln1_g   = (const float*)d_in[5];
    const float* ln1_b   = (const float*)d_in[6];
    const float* qw      = (const float*)d_in[7];
    const float* qb      = (const float*)d_in[8];
    const float* kw      = (const float*)d_in[9];
    const float* kb      = (const float*)d_in[10];
    const float* vw      = (const float*)d_in[11];
    const float* vb      = (const float*)d_in[12];
    const float* ow      = (const float*)d_in[13];
    const float* ob      = (const float*)d_in[14];
    const float* ln2_g   = (const float*)d_in[15];
    const float* ln2_b   = (const float*)d_in[16];
    const float* fcw     = (const float*)d_in[17];
    const float* fcb     = (const float*)d_in[18];
    const float* pw      = (const float*)d_in[19];
    const float* pb      = (const float*)d_in[20];
    const float* lnf_g   = (const float*)d_in[21];
    const float* lnf_b   = (const float*)d_in[22];
    const float* head_w  = (const float*)d_in[23];
    const float* head_b  = (const float*)d_in[24];
    float* out = (float*)d_out;
    (void)in_sizes; (void)n_in; (void)out_size;

    float *bt, *bemb, *bh, *by, *bq, *bk, *bv, *bao, *bmlp, *bcls;
    cudaGetSymbolAddress((void**)&bt,   g_t);
    cudaGetSymbolAddress((void**)&bemb, g_emb);
    cudaGetSymbolAddress((void**)&bh,   g_h);
    cudaGetSymbolAddress((void**)&by,   g_y);
    cudaGetSymbolAddress((void**)&bq,   g_q);
    cudaGetSymbolAddress((void**)&bk,   g_k);
    cudaGetSymbolAddress((void**)&bv,   g_v);
    cudaGetSymbolAddress((void**)&bao,  g_ao);
    cudaGetSymbolAddress((void**)&bmlp, g_mlp);
    cudaGetSymbolAddress((void**)&bcls, g_cls);

    // Patch embed
    patch_k<<<(MPATCH*DD + 255)/256, 256>>>(x, bt);
    gemm_tf32_k<<<dim3(DD/128, MPATCH/128), 256>>>(bt, proj_w, proj_b, bemb, MPATCH, DD, DD, 0);
    assemble_k<<<(BB*NTOK*DD + 255)/256, 256>>>(bemb, cls_emb, pos_emb, bh);

    const int MB = MPAD / 128;  // 37
    for (int l = 0; l < LL; l++) {
        const size_t wo  = (size_t)l * DD * DD;
        const size_t wfc = (size_t)l * DD * MLPD;

        ln_k<<<MTOK, 256>>>(bh, by, ln1_g + l*DD, ln1_b + l*DD, DD);
        gemm_tf32_k<<<dim3(DD/128, MB), 256>>>(by, qw + wo, qb + l*DD, bq, MPAD, DD, DD, 0);
        gemm_tf32_k<<<dim3(DD/128, MB), 256>>>(by, kw + wo, kb + l*DD, bk, MPAD, DD, DD, 0);
        gemm_tf32_k<<<dim3(DD/128, MB), 256>>>(by, vw + wo, vb + l*DD, bv, MPAD, DD, DD, 0);
        attn_k<<<dim3(NTOK, NHH, BB), 256>>>(bq, bk, bv, bao);
        gemm_tf32_k<<<dim3(DD/128, MB), 256>>>(bao, ow + wo, ob + l*DD, bh, MPAD, DD, DD, 1);

        ln_k<<<MTOK, 256>>>(bh, by, ln2_g + l*DD, ln2_b + l*DD, DD);
        gemm_tf32_k<<<dim3(MLPD/128, MB), 256>>>(by, fcw + wfc, fcb + l*MLPD, bmlp, MPAD, MLPD, DD, 2);
        gemm_tf32_k<<<dim3(DD/128, MB), 256>>>(bmlp, pw + wfc, pb + l*DD, bh, MPAD, DD, MLPD, 1);
    }

    ln_k<<<BB, 256>>>(bh, bcls, lnf_g, lnf_b, (long)NTOK * DD);
    head_k<<<(BB*NCLS + 255)/256, 256>>>(bcls, head_w, head_b, out);
}

// round 8
// speedup vs baseline: 8.8221x; 7.7276x over previous
#include <cuda_runtime.h>
#include <math.h>

// ---------------- Config ----------------
#define BB     8
#define CC     3
#define HH     384
#define WW     384
#define PP     16
#define DD     768
#define NHH    12
#define MLPD   3072
#define LL     12
#define NCLS   1000
#define NPAT   576
#define NTOK   577
#define HDIM   64
#define MTOK   (BB*NTOK)    // 4616
#define MPAD   4736         // 37*128
#define MPATCH (BB*NPAT)    // 4608 = 36*128

// ---------------- Scratch (device globals; .bss zero-init) ----------------
__device__ float g_t  [MPATCH*DD];
__device__ float g_emb[MPATCH*DD];
__device__ float g_h  [MPAD*DD];
__device__ float g_y  [MPAD*DD];
__device__ float g_q  [MPAD*DD];
__device__ float g_k  [MPAD*DD];
__device__ float g_v  [MPAD*DD];
__device__ float g_ao [MPAD*DD];
__device__ float g_mlp[MPAD*MLPD];
__device__ float g_cls[BB*DD];

// ---------------- Patch gather (faithful batch-mixing flatten) ----------------
__global__ void patch_k(const float* __restrict__ x, float* __restrict__ t) {
    int idx = blockIdx.x * 256 + threadIdx.x;
    if (idx >= MPATCH * DD) return;
    int p1  = idx / 221184;          // B*C*GH*GW*P
    int rem = idx % 221184;
    int b   = rem / 27648;  rem %= 27648;
    int c   = rem / 9216;   rem %= 9216;
    int gh  = rem / 384;    rem %= 384;
    int gw  = rem / 16;
    int p2  = rem % 16;
    t[idx] = x[(((b*CC + c)*HH) + gh*PP + p1) * WW + gw*PP + p2];
}

// ---------------- Assemble: CLS + pos_emb ----------------
__global__ void assemble_k(const float* __restrict__ emb, const float* __restrict__ cls_emb,
                           const float* __restrict__ pos, float* __restrict__ h) {
    int idx = blockIdx.x * 256 + threadIdx.x;
    if (idx >= BB * NTOK * DD) return;
    int d = idx % DD;
    int n = (idx / DD) % NTOK;
    int b = idx / (DD * NTOK);
    float val = (n == 0) ? cls_emb[d] : emb[((size_t)b*NPAT + (n-1))*DD + d];
    h[idx] = val + pos[n*DD + d];
}

// ---------------- TF32 tensor-core GEMM ----------------
#define APAD 20
#define BPAD 136

__device__ __forceinline__ unsigned f2tf32(float x) {
    unsigned u;
    asm("cvt.rna.tf32.f32 %0, %1;" : "=r"(u) : "f"(x));
    return u;
}

__device__ __forceinline__ void mma_tf32(float* d, const unsigned* a, const unsigned* b) {
    asm volatile(
        "mma.sync.aligned.m16n8k8.row.col.f32.tf32.tf32.f32 "
        "{%0,%1,%2,%3}, {%4,%5,%6,%7}, {%8,%9}, {%0,%1,%2,%3};"
        : "+f"(d[0]), "+f"(d[1]), "+f"(d[2]), "+f"(d[3])
        : "r"(a[0]), "r"(a[1]), "r"(a[2]), "r"(a[3]), "r"(b[0]), "r"(b[1]));
}

__global__ void __launch_bounds__(256, 2)
gemm_tf32_k(const float* __restrict__ A, const float* __restrict__ W,
            const float* __restrict__ bias, float* __restrict__ C,
            int M, int N, int K, int mode) {
    __shared__ unsigned As[128 * APAD];
    __shared__ unsigned Bs[16 * BPAD];

    const int tid  = threadIdx.x;
    const int lane = tid & 31;
    const int warp = tid >> 5;
    const int wm   = warp & 1;
    const int wn   = warp >> 1;
    const int gid  = lane >> 2;
    const int tig  = lane & 3;
    const int row0 = blockIdx.y * 128;
    const int col0 = blockIdx.x * 128;

    float acc[4][4][4];
#pragma unroll
    for (int i = 0; i < 4; i++)
#pragma unroll
        for (int j = 0; j < 4; j++)
#pragma unroll
            for (int c = 0; c < 4; c++) acc[i][j][c] = 0.f;

    for (int k0 = 0; k0 < K; k0 += 16) {
#pragma unroll
        for (int it = 0; it < 2; it++) {
            int idx = tid + it * 256;
            int r = idx >> 2, c4 = (idx & 3) << 2;
            float4 v = *reinterpret_cast<const float4*>(&A[(size_t)(row0 + r) * K + k0 + c4]);
            unsigned* dst = &As[r * APAD + c4];
            dst[0] = f2tf32(v.x); dst[1] = f2tf32(v.y);
            dst[2] = f2tf32(v.z); dst[3] = f2tf32(v.w);
        }
#pragma unroll
        for (int it = 0; it < 2; it++) {
            int idx = tid + it * 256;
            int kk = idx >> 5, n4 = (idx & 31) << 2;
            float4 v = *reinterpret_cast<const float4*>(&W[(size_t)(k0 + kk) * N + col0 + n4]);
            unsigned* dst = &Bs[kk * BPAD + n4];
            dst[0] = f2tf32(v.x); dst[1] = f2tf32(v.y);
            dst[2] = f2tf32(v.z); dst[3] = f2tf32(v.w);
        }
        __syncthreads();

#pragma unroll
        for (int ks = 0; ks < 16; ks += 8) {
            unsigned af[4][4], bf[4][2];
#pragma unroll
            for (int mt = 0; mt < 4; mt++) {
                int r = wm * 64 + mt * 16 + gid;
                af[mt][0] = As[(r    ) * APAD + ks + tig    ];
                af[mt][1] = As[(r + 8) * APAD + ks + tig    ];
                af[mt][2] = As[(r    ) * APAD + ks + tig + 4];
                af[mt][3] = As[(r + 8) * APAD + ks + tig + 4];
            }
#pragma unroll
            for (int nt = 0; nt < 4; nt++) {
                int n = wn * 32 + nt * 8 + gid;
                bf[nt][0] = Bs[(ks + tig    ) * BPAD + n];
                bf[nt][1] = Bs[(ks + tig + 4) * BPAD + n];
            }
#pragma unroll
            for (int mt = 0; mt < 4; mt++)
#pragma unroll
                for (int nt = 0; nt < 4; nt++)
                    mma_tf32(acc[mt][nt], af[mt], bf[nt]);
        }
        __syncthreads();
    }

#pragma unroll
    for (int mt = 0; mt < 4; mt++) {
#pragma unroll
        for (int nt = 0; nt < 4; nt++) {
#pragma unroll
            for (int c = 0; c < 4; c++) {
                int r   = row0 + wm * 64 + mt * 16 + gid + ((c >> 1) << 3);
                int col = col0 + wn * 32 + nt * 8 + tig * 2 + (c & 1);
                if (r >= M) continue;
                float v = acc[mt][nt][c] + bias[col];
                if (mode == 1)      v += C[(size_t)r * N + col];
                else if (mode == 2) v = 0.5f * v * (1.0f + erff(v * 0.70710678118654752f));
                C[(size_t)r * N + col] = v;
            }
        }
    }
}

// ---------------- LayerNorm ----------------
__global__ void ln_k(const float* __restrict__ in, float* __restrict__ out,
                     const float* __restrict__ g, const float* __restrict__ b,
                     long in_stride) {
    const int row = blockIdx.x;
    const float* x = in + (size_t)row * in_stride;
    float* o = out + (size_t)row * DD;
    __shared__ float red[256];
    const int tid = threadIdx.x;

    float s = 0.f;
    for (int i = tid; i < DD; i += 256) s += x[i];
    red[tid] = s; __syncthreads();
    for (int off = 128; off > 0; off >>= 1) { if (tid < off) red[tid] += red[tid + off]; __syncthreads(); }
    const float mean = red[0] * (1.0f / DD);
    __syncthreads();

    float vs = 0.f;
    for (int i = tid; i < DD; i += 256) { float d = x[i] - mean; vs += d * d; }
    red[tid] = vs; __syncthreads();
    for (int off = 128; off > 0; off >>= 1) { if (tid < off) red[tid] += red[tid + off]; __syncthreads(); }
    const float rstd = rsqrtf(red[0] * (1.0f / DD) + 1e-5f);

    for (int i = tid; i < DD; i += 256) o[i] = (x[i] - mean) * rstd * g[i] + b[i];
}

// ---------------- Flash attention: block = (b, h, 64-query tile) ----------------
// smem: Qt[d][q] (64x68), Kt[d][k] (64x68, reused as Pt[k][q]), Vs[k][d] (64x68)
#define FPAD 68
#define FA_SMEM (3 * 64 * FPAD * sizeof(float))

__global__ void __launch_bounds__(256)
fattn_k(const float* __restrict__ q, const float* __restrict__ k,
        const float* __restrict__ v, float* __restrict__ out) {
    extern __shared__ float sm[];
    float* Qt = sm;                  // [64][FPAD]  d-major
    float* Kt = sm + 64 * FPAD;      // [64][FPAD]  d-major; reused as Pt[k][q]
    float* Vs = sm + 2 * 64 * FPAD;  // [64][FPAD]  k-major

    const int tid = threadIdx.x;
    const int ty  = tid >> 4;        // 0..15 -> 4 queries each
    const int tx  = tid & 15;        // 0..15 -> 4 keys / 4 dims each
    const int qt0 = blockIdx.x * 64;
    const int h   = blockIdx.y;
    const int b   = blockIdx.z;
    const size_t base = ((size_t)b * NTOK) * DD + (size_t)h * HDIM;

    // Load Q tile transposed (coalesced global, scatter to d-major smem)
#pragma unroll
    for (int it = 0; it < 4; it++) {
        int l = tid + it * 256;             // 0..1023
        int row = l >> 4;                   // local q 0..63
        int d4  = (l & 15) << 2;            // 0..60
        float4 val = *reinterpret_cast<const float4*>(&q[base + (size_t)(qt0 + row) * DD + d4]);
        Qt[(d4 + 0) * FPAD + row] = val.x;
        Qt[(d4 + 1) * FPAD + row] = val.y;
        Qt[(d4 + 2) * FPAD + row] = val.z;
        Qt[(d4 + 3) * FPAD + row] = val.w;
    }

    float O[4][4];
    float m_run[4], l_run[4];
#pragma unroll
    for (int i = 0; i < 4; i++) {
        m_run[i] = -1e30f; l_run[i] = 0.f;
#pragma unroll
        for (int j = 0; j < 4; j++) O[i][j] = 0.f;
    }
    __syncthreads();

    for (int kt0 = 0; kt0 < NTOK; kt0 += 64) {
        // Load K (transposed) and V tiles
#pragma unroll
        for (int it = 0; it < 4; it++) {
            int l = tid + it * 256;
            int row = l >> 4;
            int d4  = (l & 15) << 2;
            const size_t goff = base + (size_t)(kt0 + row) * DD + d4;
            float4 kv = *reinterpret_cast<const float4*>(&k[goff]);
            Kt[(d4 + 0) * FPAD + row] = kv.x;
            Kt[(d4 + 1) * FPAD + row] = kv.y;
            Kt[(d4 + 2) * FPAD + row] = kv.z;
            Kt[(d4 + 3) * FPAD + row] = kv.w;
            float4 vv = *reinterpret_cast<const float4*>(&v[goff]);
            *reinterpret_cast<float4*>(&Vs[row * FPAD + d4]) = vv;
        }
        __syncthreads();

        // S = Q @ K^T (4x4 micro-tile per thread)
        float S[4][4];
#pragma unroll
        for (int i = 0; i < 4; i++)
#pragma unroll
            for (int j = 0; j < 4; j++) S[i][j] = 0.f;

#pragma unroll 8
        for (int d = 0; d < HDIM; d++) {
            float4 a  = *reinterpret_cast<const float4*>(&Qt[d * FPAD + ty * 4]);
            float4 bq = *reinterpret_cast<const float4*>(&Kt[d * FPAD + tx * 4]);
            const float av[4] = {a.x, a.y, a.z, a.w};
            const float bv[4] = {bq.x, bq.y, bq.z, bq.w};
#pragma unroll
            for (int i = 0; i < 4; i++)
#pragma unroll
                for (int j = 0; j < 4; j++) S[i][j] = fmaf(av[i], bv[j], S[i][j]);
        }
        __syncthreads();   // everyone done reading Kt before it becomes Pt

        // scale + mask
#pragma unroll
        for (int i = 0; i < 4; i++)
#pragma unroll
            for (int j = 0; j < 4; j++) {
                S[i][j] *= 0.125f;
                if (kt0 + tx * 4 + j >= NTOK) S[i][j] = -1e30f;
            }

        // online softmax (row groups = 16 lanes sharing ty; xor<=8 stays in group)
#pragma unroll
        for (int i = 0; i < 4; i++) {
            float tm = fmaxf(fmaxf(S[i][0], S[i][1]), fmaxf(S[i][2], S[i][3]));
#pragma unroll
            for (int off = 8; off > 0; off >>= 1)
                tm = fmaxf(tm, __shfl_xor_sync(0xffffffffu, tm, off));
            float mn = fmaxf(m_run[i], tm);
            float alpha = expf(m_run[i] - mn);
            float ls = 0.f;
#pragma unroll
            for (int j = 0; j < 4; j++) {
                float p = expf(S[i][j] - mn);
                S[i][j] = p;
                ls += p;
            }
#pragma unroll
            for (int off = 8; off > 0; off >>= 1)
                ls += __shfl_xor_sync(0xffffffffu, ls, off);
            l_run[i] = l_run[i] * alpha + ls;
            m_run[i] = mn;
#pragma unroll
            for (int j = 0; j < 4; j++) O[i][j] *= alpha;
        }

        // write P transposed into Kt buffer: Pt[k][q]
#pragma unroll
        for (int j = 0; j < 4; j++)
#pragma unroll
            for (int i = 0; i < 4; i++)
                Kt[(tx * 4 + j) * FPAD + ty * 4 + i] = S[i][j];
        __syncthreads();

        // O += P @ V
#pragma unroll 8
        for (int kk = 0; kk < 64; kk++) {
            float4 p  = *reinterpret_cast<const float4*>(&Kt[kk * FPAD + ty * 4]);
            float4 vv = *reinterpret_cast<const float4*>(&Vs[kk * FPAD + tx * 4]);
            const float pv[4] = {p.x, p.y, p.z, p.w};
            const float vvv[4] = {vv.x, vv.y, vv.z, vv.w};
#pragma unroll
            for (int i = 0; i < 4; i++)
#pragma unroll
                for (int j = 0; j < 4; j++) O[i][j] = fmaf(pv[i], vvv[j], O[i][j]);
        }
        __syncthreads();   // before next tile overwrites Kt/Vs
    }

    // write output
#pragma unroll
    for (int i = 0; i < 4; i++) {
        int qg = qt0 + ty * 4 + i;
        if (qg >= NTOK) continue;
        float inv = 1.0f / l_run[i];
        float4 o4 = make_float4(O[i][0] * inv, O[i][1] * inv, O[i][2] * inv, O[i][3] * inv);
        *reinterpret_cast<float4*>(&out[base + (size_t)qg * DD + tx * 4]) = o4;
    }
}

// ---------------- Head ----------------
__global__ void head_k(const float* __restrict__ cls, const float* __restrict__ hw,
                       const float* __restrict__ hb, float* __restrict__ out) {
    int idx = blockIdx.x * 256 + threadIdx.x;
    if (idx >= BB * NCLS) return;
    int b = idx / NCLS, c = idx % NCLS;
    const float* xr = &cls[b * DD];
    float acc = hb[c];
    for (int kk = 0; kk < DD; kk++) acc = fmaf(xr[kk], hw[kk * NCLS + c], acc);
    out[idx] = acc;
}

// ---------------- Launch ----------------
extern "C" void kernel_launch(void* const* d_in, const int* in_sizes, int n_in,
                              void* d_out, int out_size) {
    const float* x       = (const float*)d_in[0];
    const float* proj_w  = (const float*)d_in[1];
    const float* proj_b  = (const float*)d_in[2];
    const float* cls_emb = (const float*)d_in[3];
    const float* pos_emb = (const float*)d_in[4];
    const float* ln1_g   = (const float*)d_in[5];
    const float* ln1_b   = (const float*)d_in[6];
    const float* qw      = (const float*)d_in[7];
    const float* qb      = (const float*)d_in[8];
    const float* kw      = (const float*)d_in[9];
    const float* kb      = (const float*)d_in[10];
    const float* vw      = (const float*)d_in[11];
    const float* vb      = (const float*)d_in[12];
    const float* ow      = (const float*)d_in[13];
    const float* ob      = (const float*)d_in[14];
    const float* ln2_g   = (const float*)d_in[15];
    const float* ln2_b   = (const float*)d_in[16];
    const float* fcw     = (const float*)d_in[17];
    const float* fcb     = (const float*)d_in[18];
    const float* pw      = (const float*)d_in[19];
    const float* pb      = (const float*)d_in[20];
    const float* lnf_g   = (const float*)d_in[21];
    const float* lnf_b   = (const float*)d_in[22];
    const float* head_w  = (const float*)d_in[23];
    const float* head_b  = (const float*)d_in[24];
    float* out = (float*)d_out;
    (void)in_sizes; (void)n_in; (void)out_size;

    float *bt, *bemb, *bh, *by, *bq, *bk, *bv, *bao, *bmlp, *bcls;
    cudaGetSymbolAddress((void**)&bt,   g_t);
    cudaGetSymbolAddress((void**)&bemb, g_emb);
    cudaGetSymbolAddress((void**)&bh,   g_h);
    cudaGetSymbolAddress((void**)&by,   g_y);
    cudaGetSymbolAddress((void**)&bq,   g_q);
    cudaGetSymbolAddress((void**)&bk,   g_k);
    cudaGetSymbolAddress((void**)&bv,   g_v);
    cudaGetSymbolAddress((void**)&bao,  g_ao);
    cudaGetSymbolAddress((void**)&bmlp, g_mlp);
    cudaGetSymbolAddress((void**)&bcls, g_cls);

    cudaFuncSetAttribute(fattn_k, cudaFuncAttributeMaxDynamicSharedMemorySize, (int)FA_SMEM);

    // Patch embed
    patch_k<<<(MPATCH*DD + 255)/256, 256>>>(x, bt);
    gemm_tf32_k<<<dim3(DD/128, MPATCH/128), 256>>>(bt, proj_w, proj_b, bemb, MPATCH, DD, DD, 0);
    assemble_k<<<(BB*NTOK*DD + 255)/256, 256>>>(bemb, cls_emb, pos_emb, bh);

    const int MB = MPAD / 128;  // 37
    const int QTILES = (NTOK + 63) / 64;  // 10
    for (int l = 0; l < LL; l++) {
        const size_t wo  = (size_t)l * DD * DD;
        const size_t wfc = (size_t)l * DD * MLPD;

        ln_k<<<MTOK, 256>>>(bh, by, ln1_g + l*DD, ln1_b + l*DD, DD);
        gemm_tf32_k<<<dim3(DD/128, MB), 256>>>(by, qw + wo, qb + l*DD, bq, MPAD, DD, DD, 0);
        gemm_tf32_k<<<dim3(DD/128, MB), 256>>>(by, kw + wo, kb + l*DD, bk, MPAD, DD, DD, 0);
        gemm_tf32_k<<<dim3(DD/128, MB), 256>>>(by, vw + wo, vb + l*DD, bv, MPAD, DD, DD, 0);
        fattn_k<<<dim3(QTILES, NHH, BB), 256, FA_SMEM>>>(bq, bk, bv, bao);
        gemm_tf32_k<<<dim3(DD/128, MB), 256>>>(bao, ow + wo, ob + l*DD, bh, MPAD, DD, DD, 1);

        ln_k<<<MTOK, 256>>>(bh, by, ln2_g + l*DD, ln2_b + l*DD, DD);
        gemm_tf32_k<<<dim3(MLPD/128, MB), 256>>>(by, fcw + wfc, fcb + l*MLPD, bmlp, MPAD, MLPD, DD, 2);
        gemm_tf32_k<<<dim3(DD/128, MB), 256>>>(bmlp, pw + wfc, pb + l*DD, bh, MPAD, DD, MLPD, 1);
    }

    ln_k<<<BB, 256>>>(bh, bcls, lnf_g, lnf_b, (long)NTOK * DD);
    head_k<<<(BB*NCLS + 255)/256, 256>>>(bcls, head_w, head_b, out);
}